// round 16
// baseline (speedup 1.0000x reference)
#include <cuda_runtime.h>
#include <cuda_bf16.h>
#include <math.h>
#include <cstdint>

#define E_EDGES 200000
#define NN 10000
#define F 128
#define BM 128
#define NB 1563
#define PI_OVER_L 0.31415926535897932f
#define AP 40     // B chunk smem pitch in bf16 (32 k + 8 pad)
#define FP 136    // full K=128 A pitch in bf16
#define PHP 264   // full K=256 A pitch in bf16

// ------------------------- device scratch (no-alloc path) -------------------
__device__ __align__(16) unsigned g_hphi_img[(size_t)E_EDGES * 128]; // words 0..63 hi pairs, 64..127 lo pairs
__device__ __align__(16) unsigned g_hw_img  [(size_t)E_EDGES * 128];
__device__ float g_m[(size_t)3 * E_EDGES * F];                       // gates / cp / scale
__device__ __align__(16) __nv_bfloat16 g_W1p_bf[2 * 128 * 256];      // [term][n][k]
__device__ __align__(16) __nv_bfloat16 g_W1w_bf[2 * 128 * 128];
__device__ __align__(16) __nv_bfloat16 g_W2p_bf[5 * 2 * 128 * 128];  // [c][term][n][k]
__device__ __align__(16) __nv_bfloat16 g_W2w_bf[5 * 2 * 128 * 128];

// ------------------------------ helpers -------------------------------------
__device__ __forceinline__ float silu_f(float x) { return x / (1.0f + expf(-x)); }

__device__ __forceinline__ uint32_t smem_u32(const void* p) {
    uint32_t a;
    asm("{ .reg .u64 t; cvta.to.shared.u64 t, %1; cvt.u32.u64 %0, t; }" : "=r"(a) : "l"(p));
    return a;
}
__device__ __forceinline__ void red_add4(float* p, float a, float b, float c, float d) {
    asm volatile("red.global.add.v4.f32 [%0], {%1,%2,%3,%4};"
                 :: "l"(p), "f"(a), "f"(b), "f"(c), "f"(d) : "memory");
}
__device__ __forceinline__ void red_add2(float* p, float a, float b) {
    asm volatile("red.global.add.v2.f32 [%0], {%1,%2};"
                 :: "l"(p), "f"(a), "f"(b) : "memory");
}
__device__ __forceinline__ void split_pack(float a, float b, unsigned& hi, unsigned& lo) {
    __nv_bfloat16 ah = __float2bfloat16(a), bh = __float2bfloat16(b);
    hi = ((unsigned)*(unsigned short*)&bh << 16) | (unsigned)*(unsigned short*)&ah;
    __nv_bfloat16 al = __float2bfloat16(a - __bfloat162float(ah));
    __nv_bfloat16 bl = __float2bfloat16(b - __bfloat162float(bh));
    lo = ((unsigned)*(unsigned short*)&bl << 16) | (unsigned)*(unsigned short*)&al;
}
__device__ __forceinline__ void mma_bf16(float* c, const unsigned* a, const unsigned* b) {
    asm volatile("mma.sync.aligned.m16n8k16.row.col.f32.bf16.bf16.f32 "
        "{%0,%1,%2,%3}, {%4,%5,%6,%7}, {%8,%9}, {%0,%1,%2,%3};"
        : "+f"(c[0]), "+f"(c[1]), "+f"(c[2]), "+f"(c[3])
        : "r"(a[0]), "r"(a[1]), "r"(a[2]), "r"(a[3]), "r"(b[0]), "r"(b[1]));
}
__device__ __forceinline__ void ldsm4(unsigned* r, uint32_t saddr) {
    asm volatile("ldmatrix.sync.aligned.m8n8.x4.shared.b16 {%0,%1,%2,%3}, [%4];"
        : "=r"(r[0]), "=r"(r[1]), "=r"(r[2]), "=r"(r[3]) : "r"(saddr));
}
__device__ __forceinline__ void cp16(uint32_t d, const void* s) {
    asm volatile("cp.async.cg.shared.global [%0], [%1], 16;" :: "r"(d), "l"(s));
}
#define CP_COMMIT() asm volatile("cp.async.commit_group;" ::: "memory")
#define CP_WAIT0()  asm volatile("cp.async.wait_group 0;" ::: "memory")

// one K=32 chunk, warp tile M16 x N64, 3-term bf16 split, ldmatrix fragments.
// MMAs grouped by term across pairs of n-tiles so same-accumulator reuse
// distance is 4 independent MMAs (hides HMMA latency).
template<int PITCH>
__device__ __forceinline__ void mma_chunk_ld(
    float (*acc)[4], uint32_t AhB, uint32_t AlB, uint32_t BhB, uint32_t BlB, int lane)
{
    const int grp = lane >> 3, r = lane & 7;
    const uint32_t arow = (uint32_t)((grp & 1) * 8 + r);
    const uint32_t acol = (uint32_t)((grp >> 1) * 8);
    const uint32_t brow = (uint32_t)((grp >> 1) * 8 + r);
    const uint32_t bcol = (uint32_t)((grp & 1) * 8);
    #pragma unroll
    for (int ks = 0; ks < 2; ks++) {
        const uint32_t k0 = (uint32_t)(ks * 16);
        const uint32_t aoff = (arow * PITCH + k0 + acol) * 2;
        unsigned ah[4], al[4];
        ldsm4(ah, AhB + aoff);
        ldsm4(al, AlB + aoff);
        #pragma unroll
        for (int jp = 0; jp < 2; jp++) {
            unsigned bh[2][4], bl[2][4];
            #pragma unroll
            for (int u = 0; u < 2; u++) {
                const uint32_t boff =
                    ((uint32_t)((jp * 2 + u) * 16) + brow) * (AP * 2) + (k0 + bcol) * 2;
                ldsm4(bh[u], BhB + boff);
                ldsm4(bl[u], BlB + boff);
            }
            // term 1: ah x bh   (4 independent MMAs)
            #pragma unroll
            for (int u = 0; u < 2; u++) {
                const int jj = jp * 2 + u;
                mma_bf16(acc[jj * 2],     ah, bh[u]);
                mma_bf16(acc[jj * 2 + 1], ah, bh[u] + 2);
            }
            // term 2: ah x bl
            #pragma unroll
            for (int u = 0; u < 2; u++) {
                const int jj = jp * 2 + u;
                mma_bf16(acc[jj * 2],     ah, bl[u]);
                mma_bf16(acc[jj * 2 + 1], ah, bl[u] + 2);
            }
            // term 3: al x bh
            #pragma unroll
            for (int u = 0; u < 2; u++) {
                const int jj = jp * 2 + u;
                mma_bf16(acc[jj * 2],     al, bh[u]);
                mma_bf16(acc[jj * 2 + 1], al, bh[u] + 2);
            }
        }
    }
}

// async-load one B chunk (128n x 32k valid, hi+lo) into dst (u32 smem addr).
// 1024 x 16B ops, 512 threads -> 2 per thread. NO commit inside.
__device__ __forceinline__ void cp_b_chunk(
    uint32_t dst, const __nv_bfloat16* __restrict__ sh, const __nv_bfloat16* __restrict__ sl,
    int kofs, int stride, int tid)
{
    #pragma unroll
    for (int i = 0; i < 2; i++) {
        int id = tid + i * 512;
        int term = id >> 9, r = id & 511;
        int n = r >> 2, q = r & 3;
        const __nv_bfloat16* sb = term ? sl : sh;
        cp16(dst + (uint32_t)(term * 10240 + n * 80 + q * 16),
             (const char*)(sb + n * stride + kofs) + q * 16);
    }
}

// ---------------- prep: weights -> bf16 hi/lo, N-major K-contiguous ---------
__global__ void prep_weights(const float* __restrict__ pW1, const float* __restrict__ wW1,
                             const float* __restrict__ pW2, const float* __restrict__ wW2)
{
    const int total = 32768 + 16384 + 81920 + 81920;
    for (int i = blockIdx.x * blockDim.x + threadIdx.x; i < total; i += gridDim.x * blockDim.x) {
        float v; __nv_bfloat16 *dh, *dl;
        if (i < 32768) {
            int k = i >> 7, n = i & 127;
            v = pW1[i];
            dh = g_W1p_bf + n * 256 + k; dl = dh + 32768;
        } else if (i < 49152) {
            int j = i - 32768, k = j >> 7, n = j & 127;
            v = wW1[j];
            dh = g_W1w_bf + n * 128 + k; dl = dh + 16384;
        } else if (i < 131072) {
            int j = i - 49152, k = j / 640, nn = j % 640;
            int c = nn >> 7, n = nn & 127;
            v = pW2[j];
            dh = g_W2p_bf + ((c * 2) * 128 + n) * 128 + k; dl = dh + 16384;
        } else {
            int j = i - 131072, k = j / 640, nn = j % 640;
            int c = nn >> 7, n = nn & 127;
            v = wW2[j];
            dh = g_W2w_bf + ((c * 2) * 128 + n) * 128 + k; dl = dh + 16384;
        }
        __nv_bfloat16 h = __float2bfloat16(v);
        *dh = h;
        *dl = __float2bfloat16(v - __bfloat162float(h));
    }
}

// ---------------- init: residual copy ---------------------------------------
__global__ void init_out_kernel(const float* __restrict__ eq, const float* __restrict__ inv,
                                float* __restrict__ out) {
    int i = blockIdx.x * blockDim.x + threadIdx.x;
    const int a = NN * F * 3 / 4, b = NN * F / 4;
    if (i < a) ((float4*)out)[i] = ((const float4*)eq)[i];
    else if (i < a + b) ((float4*)(out + (size_t)NN * F * 3))[i - a] = ((const float4*)inv)[i - a];
}

// ---------------- hidden: layer-1 both MLPs ---------------------------------
// dyn smem (bytes):
//  Ah 0 (67584) Al 67584 (67584)  Bbuf 135168 (2 x 20480)
//  s_src 176128 (512), s_dist 176640 (512), s_b 177152 (1024) -> 178176
#define SMH_BYTES 178176
__global__ __launch_bounds__(512, 1) void hidden_kernel(
    const int* __restrict__ src_idx, const float* __restrict__ inv_node,
    const float* __restrict__ inv_edge, const float* __restrict__ dist,
    const float* __restrict__ pb1, const float* __restrict__ wb1)
{
    extern __shared__ char sm[];
    __nv_bfloat16* Ah = (__nv_bfloat16*)sm;
    __nv_bfloat16* Al = (__nv_bfloat16*)(sm + 67584);
    int*   s_src  = (int*)(sm + 176128);
    float* s_dist = (float*)(sm + 176640);
    float* s_b    = (float*)(sm + 177152);

    const uint32_t smb = smem_u32(sm);
    const uint32_t ah_b = smb, al_b = smb + 67584;
    const uint32_t bbuf = smb + 135168;

    const int tid = threadIdx.x;
    const int w = tid >> 5, lane = tid & 31;
    const int g = lane >> 2, t = lane & 3;
    const int wm = w & 7, wn = w >> 3;
    const int e0 = blockIdx.x * BM;

    // preload B chunk 0 (phi kc=0) async, group 0
    cp_b_chunk(bbuf, g_W1p_bf, g_W1p_bf + 32768, 0, 256, tid);
    CP_COMMIT();

    if (tid < 128) {
        int e = e0 + tid; if (e >= E_EDGES) e = E_EDGES - 1;
        s_src[tid] = src_idx[e];
        s_dist[tid] = dist[e] * PI_OVER_L;
    }
    if (tid >= 128 && tid < 384) {
        int i = tid - 128;
        s_b[i] = (i < 128) ? pb1[i] : wb1[i - 128];
    }
    __syncthreads();   // s_src visible for A build

    // ---- build full phi A (K=256, pitch PHP) ----
    #pragma unroll
    for (int i = 0; i < 16; i++) {
        int slot = tid + i * 512;
        int row = slot >> 6, q = slot & 63;
        int kglob = q * 4;
        const float* p;
        if (kglob < 128) p = inv_node + (size_t)s_src[row] * F + kglob;
        else {
            int e = e0 + row; if (e >= E_EDGES) e = E_EDGES - 1;
            p = inv_edge + (size_t)e * F + (kglob - 128);
        }
        float4 v = *(const float4*)p;
        unsigned h01, l01, h23, l23;
        split_pack(v.x, v.y, h01, l01);
        split_pack(v.z, v.w, h23, l23);
        *(uint2*)&Ah[row * PHP + q * 4] = make_uint2(h01, h23);
        *(uint2*)&Al[row * PHP + q * 4] = make_uint2(l01, l23);
    }

    float acc[8][4];
    #pragma unroll
    for (int j = 0; j < 8; j++)
        #pragma unroll
        for (int q = 0; q < 4; q++) acc[j][q] = 0.0f;

    const uint32_t b_wn = (uint32_t)(wn * 64 * AP * 2);

    // ---- phi: K=256, 8 chunks; 1 bar per chunk, cp.async pipelined ----
    for (int kc = 0; kc < 8; kc++) {
        CP_WAIT0();
        __syncthreads();   // B(kc) + (kc==0: A) visible; all warps done with buf[(kc+1)&1]
        if (kc < 7)
            cp_b_chunk(bbuf + ((kc + 1) & 1) * 20480,
                       g_W1p_bf, g_W1p_bf + 32768, (kc + 1) * 32, 256, tid);
        else  // chunk 8 = w side kc0 -> buf0
            cp_b_chunk(bbuf, g_W1w_bf, g_W1w_bf + 16384, 0, 128, tid);
        CP_COMMIT();
        uint32_t bb = bbuf + (kc & 1) * 20480 + b_wn;
        mma_chunk_ld<PHP>(acc,
            ah_b + (uint32_t)((wm * 16 * PHP + kc * 32) * 2),
            al_b + (uint32_t)((wm * 16 * PHP + kc * 32) * 2),
            bb, bb + 10240, lane);
    }
    {   // epilogue phi
        #pragma unroll
        for (int j = 0; j < 8; j++) {
            int col = wn * 64 + j * 8 + 2 * t;
            int word = wn * 32 + 4 * j + t;
            float b0 = s_b[col], b1 = s_b[col + 1];
            int e0r = e0 + wm * 16 + g, e1r = e0r + 8;
            unsigned hi, lo;
            if (e0r < E_EDGES) {
                split_pack(silu_f(acc[j][0] + b0), silu_f(acc[j][1] + b1), hi, lo);
                g_hphi_img[(size_t)e0r * 128 + word] = hi;
                g_hphi_img[(size_t)e0r * 128 + 64 + word] = lo;
            }
            if (e1r < E_EDGES) {
                split_pack(silu_f(acc[j][2] + b0), silu_f(acc[j][3] + b1), hi, lo);
                g_hphi_img[(size_t)e1r * 128 + word] = hi;
                g_hphi_img[(size_t)e1r * 128 + 64 + word] = lo;
            }
        }
    }
    __syncthreads();   // all phi MMAs done before A rebuild

    // ---- build PE A (K=128, pitch FP) ----
    #pragma unroll
    for (int i = 0; i < 8; i++) {
        int slot = tid + i * 512;
        int row = slot >> 5, q = slot & 31;
        int kglob = q * 4;
        float d = s_dist[row];
        float v[4];
        #pragma unroll
        for (int kk = 0; kk < 4; kk++) {
            int r = kglob + kk;
            v[kk] = (r < 64) ? __sinf(d * (float)r) : __cosf(d * (float)(r - 64));
        }
        unsigned h01, l01, h23, l23;
        split_pack(v[0], v[1], h01, l01);
        split_pack(v[2], v[3], h23, l23);
        *(uint2*)&Ah[row * FP + q * 4] = make_uint2(h01, h23);
        *(uint2*)&Al[row * FP + q * 4] = make_uint2(l01, l23);
    }

    #pragma unroll
    for (int j = 0; j < 8; j++)
        #pragma unroll
        for (int q = 0; q < 4; q++) acc[j][q] = 0.0f;

    // ---- w: K=128, 4 chunks (global chunk 8+kc -> buf[kc&1]) ----
    for (int kc = 0; kc < 4; kc++) {
        CP_WAIT0();
        __syncthreads();   // B + rebuilt A visible
        if (kc < 3)
            cp_b_chunk(bbuf + ((kc + 1) & 1) * 20480,
                       g_W1w_bf, g_W1w_bf + 16384, (kc + 1) * 32, 128, tid);
        CP_COMMIT();
        uint32_t bb = bbuf + (kc & 1) * 20480 + b_wn;
        mma_chunk_ld<FP>(acc,
            ah_b + (uint32_t)((wm * 16 * FP + kc * 32) * 2),
            al_b + (uint32_t)((wm * 16 * FP + kc * 32) * 2),
            bb, bb + 10240, lane);
    }
    {   // epilogue w
        #pragma unroll
        for (int j = 0; j < 8; j++) {
            int col = wn * 64 + j * 8 + 2 * t;
            int word = wn * 32 + 4 * j + t;
            float b0 = s_b[128 + col], b1 = s_b[128 + col + 1];
            int e0r = e0 + wm * 16 + g, e1r = e0r + 8;
            unsigned hi, lo;
            if (e0r < E_EDGES) {
                split_pack(silu_f(acc[j][0] + b0), silu_f(acc[j][1] + b1), hi, lo);
                g_hw_img[(size_t)e0r * 128 + word] = hi;
                g_hw_img[(size_t)e0r * 128 + 64 + word] = lo;
            }
            if (e1r < E_EDGES) {
                split_pack(silu_f(acc[j][2] + b0), silu_f(acc[j][3] + b1), hi, lo);
                g_hw_img[(size_t)e1r * 128 + word] = hi;
                g_hw_img[(size_t)e1r * 128 + 64 + word] = lo;
            }
        }
    }
}

// ---------------- mm2: layer-2 both MLPs + fused dispatch -------------------
// dyn smem (bytes):
//  Aph 0 (34816) Apl 34816 Awh 69632 Awl 104448
//  Bbuf 139264: 2 pair-buffers x 40960 = 81920    (pair = [phi hi|lo][w hi|lo])
//  s_dst 221184 (512), s_pb 221696 (2560), s_wb 224256 (2560) -> 226816
#define SM2_BYTES 226816
__global__ __launch_bounds__(512, 1) void mm2_kernel(
    const int* __restrict__ dst_idx, const float* __restrict__ inv_edge,
    const float* __restrict__ pb2, const float* __restrict__ wb2,
    float* __restrict__ out)
{
    extern __shared__ char sm[];
    int*   s_dst = (int*)(sm + 221184);
    float* s_pb  = (float*)(sm + 221696);
    float* s_wb  = (float*)(sm + 224256);

    const uint32_t smb = smem_u32(sm);
    const uint32_t bbuf = smb + 139264;

    const int tid = threadIdx.x;
    const int w = tid >> 5, lane = tid & 31;
    const int g = lane >> 2, t = lane & 3;
    const int wm = w & 7, wn = w >> 3;
    const int e0 = blockIdx.x * BM;

    // A images via cp.async (group 0, together with pair 0)
    #pragma unroll
    for (int i = 0; i < 16; i++) {
        int id = tid + i * 512;
        int mat = id >> 12;
        int rem = id & 4095;
        int term = rem >> 11;
        int r2 = rem & 2047;
        int row = r2 >> 4, q = r2 & 15;
        int e = e0 + row; if (e >= E_EDGES) e = E_EDGES - 1;
        const unsigned* simg = mat ? g_hw_img : g_hphi_img;
        cp16(smb + (uint32_t)(mat * 69632 + term * 34816 + row * (FP * 2) + q * 16),
             (const char*)(simg + (size_t)e * 128) + term * 256 + q * 16);
    }
    // pair 0 = (c=0, kc=0): phi chunk + w chunk
    cp_b_chunk(bbuf,         g_W2p_bf, g_W2p_bf + 16384, 0, 128, tid);
    cp_b_chunk(bbuf + 20480, g_W2w_bf, g_W2w_bf + 16384, 0, 128, tid);
    CP_COMMIT();

    if (tid < 128) {
        int e = e0 + tid; if (e >= E_EDGES) e = E_EDGES - 1;
        s_dst[tid] = dst_idx[e];
    }
    for (int i = tid; i < 640; i += 512) { s_pb[i] = pb2[i]; s_wb[i] = wb2[i]; }

    float* out_inv  = out + (size_t)NN * F * 3;
    float* out_edge = out_inv + (size_t)NN * F;

    const int r0 = wm * 16 + g, r1 = r0 + 8;
    const int eg0 = e0 + r0, eg1 = e0 + r1;
    const bool v0 = eg0 < E_EDGES, v1 = eg1 < E_EDGES;

    const uint32_t a_ph = smb + (uint32_t)(wm * 16 * FP * 2);
    const uint32_t a_pl = a_ph + 34816;
    const uint32_t a_wh = a_ph + 69632;
    const uint32_t a_wl = a_ph + 104448;
    const uint32_t b_wn = (uint32_t)(wn * 64 * AP * 2);

    __syncthreads();   // s_dst / s_pb / s_wb visible
    const int dn0 = s_dst[r0], dn1 = s_dst[r1];

    for (int c = 0; c < 5; c++) {
        float acc1[8][4], acc2[8][4];
        #pragma unroll
        for (int j = 0; j < 8; j++)
            #pragma unroll
            for (int q = 0; q < 4; q++) { acc1[j][q] = 0.0f; acc2[j][q] = 0.0f; }

        for (int kc = 0; kc < 4; kc++) {
            const int idx = c * 4 + kc;
            CP_WAIT0();
            __syncthreads();   // pair idx visible; all warps done with buf[(idx+1)&1]
            if (idx < 19) {
                int nx = idx + 1, c2 = nx >> 2, k2 = nx & 3;
                uint32_t nb = bbuf + (uint32_t)((nx & 1) * 40960);
                cp_b_chunk(nb, g_W2p_bf + (size_t)(c2 * 2) * 16384,
                               g_W2p_bf + (size_t)(c2 * 2 + 1) * 16384, k2 * 32, 128, tid);
                cp_b_chunk(nb + 20480, g_W2w_bf + (size_t)(c2 * 2) * 16384,
                               g_W2w_bf + (size_t)(c2 * 2 + 1) * 16384, k2 * 32, 128, tid);
            }
            CP_COMMIT();
            uint32_t bb = bbuf + (uint32_t)((idx & 1) * 40960) + b_wn;
            uint32_t ko = (uint32_t)(kc * 32 * 2);
            mma_chunk_ld<FP>(acc1, a_ph + ko, a_pl + ko, bb, bb + 10240, lane);
            mma_chunk_ld<FP>(acc2, a_wh + ko, a_wl + ko, bb + 20480, bb + 30720, lane);
        }

        // ---- combine + dispatch ----
        const float* pbc = s_pb + c * 128;
        const float* wbc = s_wb + c * 128;
        #pragma unroll
        for (int j = 0; j < 8; j++) {
            int col = wn * 64 + j * 8 + 2 * t;
            float b10 = pbc[col], b11 = pbc[col + 1];
            float b20 = wbc[col], b21 = wbc[col + 1];
            float m00 = (acc1[j][0] + b10) * (acc2[j][0] + b20);
            float m01 = (acc1[j][1] + b11) * (acc2[j][1] + b21);
            float m10 = (acc1[j][2] + b10) * (acc2[j][2] + b20);
            float m11 = (acc1[j][3] + b11) * (acc2[j][3] + b21);
            if (c < 3) {
                if (v0) *(float2*)&g_m[((size_t)c * E_EDGES + eg0) * F + col] = make_float2(m00, m01);
                if (v1) *(float2*)&g_m[((size_t)c * E_EDGES + eg1) * F + col] = make_float2(m10, m11);
            } else if (c == 3) {
                if (v0) red_add2(out_inv + (size_t)dn0 * F + col, m00, m01);
                if (v1) red_add2(out_inv + (size_t)dn1 * F + col, m10, m11);
            } else {
                if (v0) {
                    float2 ie = *(const float2*)&inv_edge[(size_t)eg0 * F + col];
                    *(float2*)&out_edge[(size_t)eg0 * F + col] = make_float2(ie.x + m00, ie.y + m01);
                }
                if (v1) {
                    float2 ie = *(const float2*)&inv_edge[(size_t)eg1 * F + col];
                    *(float2*)&out_edge[(size_t)eg1 * F + col] = make_float2(ie.x + m10, ie.y + m11);
                }
            }
        }
    }
}

// ---------------- geometric epilogue (unchanged, proven) --------------------
__global__ __launch_bounds__(256) void epilogue_kernel(
    const int* __restrict__ src_idx, const int* __restrict__ dst_idx,
    const float* __restrict__ eq_node, const float* __restrict__ edir,
    float* __restrict__ out)
{
    __shared__ float s_eq[16][384];
    __shared__ int   s_node[16];
    __shared__ float s_ed[24];
    const int tid = threadIdx.x;
    const int e0  = blockIdx.x * 8;

    if (tid < 16) { int e = e0 + (tid >> 1); s_node[tid] = (tid & 1) ? dst_idx[e] : src_idx[e]; }
    if (tid < 24) s_ed[tid] = edir[(size_t)e0 * 3 + tid];
    __syncthreads();
    {
        int w = tid >> 5, lane = tid & 31;
        #pragma unroll
        for (int rr = 0; rr < 2; rr++) {
            int r = w * 2 + rr;
            const float* p = eq_node + (size_t)s_node[r] * (F * 3);
            #pragma unroll
            for (int j = 0; j < 3; j++)
                ((float4*)s_eq[r])[lane + 32 * j] = ((const float4*)p)[lane + 32 * j];
        }
    }
    __syncthreads();

    const int el = tid >> 5, fq = tid & 31;
    const int e  = e0 + el;
    float4 g4  = *(const float4*)(g_m + ((size_t)0 * E_EDGES + e) * F + fq * 4);
    float4 c4  = *(const float4*)(g_m + ((size_t)1 * E_EDGES + e) * F + fq * 4);
    float4 sc4 = *(const float4*)(g_m + ((size_t)2 * E_EDGES + e) * F + fq * 4);
    float gg[4] = {g4.x, g4.y, g4.z, g4.w};
    float cp[4] = {c4.x, c4.y, c4.z, c4.w};
    float sc[4] = {sc4.x, sc4.y, sc4.z, sc4.w};

    const float* sp = &s_eq[el * 2][fq * 12];
    const float* dp = &s_eq[el * 2 + 1][fq * 12];
    float sv[12], dv[12];
    *(float4*)&sv[0] = *(const float4*)sp;      *(float4*)&sv[4] = *(const float4*)(sp + 4);
    *(float4*)&sv[8] = *(const float4*)(sp + 8);
    *(float4*)&dv[0] = *(const float4*)dp;      *(float4*)&dv[4] = *(const float4*)(dp + 4);
    *(float4*)&dv[8] = *(const float4*)(dp + 8);

    float dx = s_ed[el * 3], dy = s_ed[el * 3 + 1], dz = s_ed[el * 3 + 2];
    float o[12];
    #pragma unroll
    for (int q = 0; q < 4; q++) {
        float vx = dv[q * 3], vy = dv[q * 3 + 1], vz = dv[q * 3 + 2];
        float cx = dy * vz - dz * vy, cy = dz * vx - dx * vz, cz = dx * vy - dy * vx;
        o[q * 3 + 0] = sc[q] * dx + gg[q] * sv[q * 3 + 0] + cp[q] * cx;
        o[q * 3 + 1] = sc[q] * dy + gg[q] * sv[q * 3 + 1] + cp[q] * cy;
        o[q * 3 + 2] = sc[q] * dz + gg[q] * sv[q * 3 + 2] + cp[q] * cz;
    }
    int dn = s_node[el * 2 + 1];
    float* op = out + (size_t)dn * (F * 3) + fq * 12;
    red_add4(op,     o[0], o[1], o[2],  o[3]);
    red_add4(op + 4, o[4], o[5], o[6],  o[7]);
    red_add4(op + 8, o[8], o[9], o[10], o[11]);
}

// ---------------------------------------------------------------------------
extern "C" void kernel_launch(void* const* d_in, const int* in_sizes, int n_in,
                              void* d_out, int out_size) {
    const int*   edge_index = (const int*)d_in[0];
    const float* inv_node   = (const float*)d_in[1];
    const float* eq_node    = (const float*)d_in[2];
    const float* inv_edge   = (const float*)d_in[3];
    const float* dist       = (const float*)d_in[4];
    const float* edir       = (const float*)d_in[5];
    const float* pW1 = (const float*)d_in[6];
    const float* pb1 = (const float*)d_in[7];
    const float* pW2 = (const float*)d_in[8];
    const float* pb2 = (const float*)d_in[9];
    const float* wW1 = (const float*)d_in[10];
    const float* wb1 = (const float*)d_in[11];
    const float* wW2 = (const float*)d_in[12];
    const float* wb2 = (const float*)d_in[13];
    float* out = (float*)d_out;

    const int* src = edge_index;
    const int* dst = edge_index + E_EDGES;

    cudaFuncSetAttribute(hidden_kernel, cudaFuncAttributeMaxDynamicSharedMemorySize, SMH_BYTES);
    cudaFuncSetAttribute(mm2_kernel, cudaFuncAttributeMaxDynamicSharedMemorySize, SM2_BYTES);

    prep_weights<<<416, 512>>>(pW1, wW1, pW2, wW2);
    init_out_kernel<<<5000, 256>>>(eq_node, inv_node, out);
    hidden_kernel<<<NB, 512, SMH_BYTES>>>(src, inv_node, inv_edge, dist, pb1, wb1);
    mm2_kernel<<<NB, 512, SM2_BYTES>>>(dst, inv_edge, pb2, wb2, out);
    epilogue_kernel<<<E_EDGES / 8, 256>>>(src, dst, eq_node, edir, out);
}